// round 15
// baseline (speedup 1.0000x reference)
#include <cuda_runtime.h>
#include <cstdint>

#define NN 50000
#define EE 1600000
#define GG 128
#define HC1 128      // 4 heads * 32 ch
#define C2 64
#define EPS_ 1e-5f
#define NBLK 196     // ceil(50000/256)

// ---------------- scratch (static device memory; no allocs) ----------------
__device__ __align__(16) float g_xl1[NN * HC1];
__device__ __align__(16) float g_xr1[NN * HC1];
__device__ __align__(16) float g_h1 [NN * HC1];
__device__ __align__(16) float g_xl2[NN * C2];
__device__ __align__(16) float g_xr2[NN * C2];
__device__ __align__(16) float g_h2 [NN * C2];
__device__ int   g_deg[NN];
__device__ int   g_off[NN + 1];
__device__ int   g_cur[NN];
__device__ int   g_csr[EE];
__device__ unsigned long long g_scan_state[NBLK];  // (inclusive<<32)|flag
__device__ float g_stats1[2 * HC1];
__device__ float g_stats2[2 * C2];

// ---------------- tf32 helpers ----------------------------------------------
__device__ __forceinline__ void tf32split(float v, uint32_t& hi, uint32_t& lo) {
    uint32_t h;
    asm("cvt.rna.tf32.f32 %0, %1;" : "=r"(h) : "f"(v));
    float r = v - __uint_as_float(h);
    uint32_t l;
    asm("cvt.rna.tf32.f32 %0, %1;" : "=r"(l) : "f"(r));
    hi = h; lo = l;
}

#define MMA_TF32(d, a0, a1, a2, a3, b0, b1)                                   \
    asm volatile("mma.sync.aligned.m16n8k8.row.col.f32.tf32.tf32.f32 "        \
                 "{%0,%1,%2,%3}, {%4,%5,%6,%7}, {%8,%9}, {%0,%1,%2,%3};"      \
                 : "+f"(d[0]), "+f"(d[1]), "+f"(d[2]), "+f"(d[3])             \
                 : "r"(a0), "r"(a1), "r"(a2), "r"(a3), "r"(b0), "r"(b1))

// ---------------- prep: zero deg, scan state, BN stats ----------------------
__global__ void prep_kernel() {
    int i = blockIdx.x * blockDim.x + threadIdx.x;
    if (i < NN) g_deg[i] = 0;
    if (i < NBLK) g_scan_state[i] = 0ull;
    if (i < 2 * HC1) g_stats1[i] = 0.f;
    if (i < 2 * C2)  g_stats2[i] = 0.f;
}

// ---------------- in-degree histogram (4 edges/thread, int4 loads) ---------
__global__ void hist_kernel(const int* __restrict__ ei) {
    int e4 = blockIdx.x * blockDim.x + threadIdx.x;
    if (e4 * 4 < EE) {
        int4 d4 = *(const int4*)&ei[EE + e4 * 4];
        int d0 = d4.x, d1 = d4.y, d2 = d4.z, d3 = d4.w;
        if ((unsigned)d0 >= NN) d0 = 0;
        if ((unsigned)d1 >= NN) d1 = 0;
        if ((unsigned)d2 >= NN) d2 = 0;
        if ((unsigned)d3 >= NN) d3 = 0;
        atomicAdd(&g_deg[d0], 1);
        atomicAdd(&g_deg[d1], 1);
        atomicAdd(&g_deg[d2], 1);
        atomicAdd(&g_deg[d3], 1);
    }
}

// ---------------- single-pass decoupled-lookback exclusive scan -------------
__global__ void scan_kernel() {
    __shared__ int s[256];
    __shared__ long long base_s;
    int t = threadIdx.x;
    int b = blockIdx.x;
    int i = b * 256 + t;

    int v = (i < NN) ? g_deg[i] : 0;
    s[t] = v;
    __syncthreads();
    for (int o = 1; o < 256; o <<= 1) {
        int tv = (t >= o) ? s[t - o] : 0;
        __syncthreads();
        s[t] += tv;
        __syncthreads();
    }
    int blockAgg = s[255];

    if (t == 0) {
        long long run = 0;
        if (b == 0) {
            atomicExch(&g_scan_state[0], ((unsigned long long)blockAgg << 32) | 2ull);
        } else {
            atomicExch(&g_scan_state[b], ((unsigned long long)blockAgg << 32) | 1ull);
            int p = b - 1;
            while (p >= 0) {
                unsigned long long st;
                do {
                    st = *(volatile unsigned long long*)&g_scan_state[p];
                } while ((st & 3ull) == 0ull);
                run += (long long)(st >> 32);
                if ((st & 3ull) == 2ull) break;
                p--;
            }
            atomicExch(&g_scan_state[b],
                       ((unsigned long long)(run + blockAgg) << 32) | 2ull);
        }
        base_s = run;
    }
    __syncthreads();
    long long base = base_s;
    int e = (int)base + s[t] - v;       // exclusive prefix
    if (i < NN) { g_off[i] = e; g_cur[i] = e; }
    if (b == NBLK - 1 && t == 255) g_off[NN] = (int)base + blockAgg;
}

// ---------------- CSR scatter (edges only; self loops handled in agg) -------
__global__ void scatter_kernel(const int* __restrict__ ei) {
    int i = blockIdx.x * blockDim.x + threadIdx.x;
    const int E4 = EE / 4;
    if (i < E4) {
        int4 s4 = *(const int4*)&ei[i * 4];
        int4 d4 = *(const int4*)&ei[EE + i * 4];
        int ss[4] = {s4.x, s4.y, s4.z, s4.w};
        int dd[4] = {d4.x, d4.y, d4.z, d4.w};
#pragma unroll
        for (int k = 0; k < 4; k++) {
            int sv = ss[k], dv = dd[k];
            if ((unsigned)sv >= NN) sv = 0;
            if ((unsigned)dv >= NN) dv = 0;
            int pos = atomicAdd(&g_cur[dv], 1);
            if ((unsigned)pos < EE) g_csr[pos] = sv;
        }
    }
}

// ---------------- GEMM1 (tf32 tensor cores, 3xTF32):
// x[50000,64] @ [W1l|W1r][64,256] + bias -> xl1, xr1 (fp32)
// block: 64 rows x 256 cols, 8 warps (4m x 2n), warp tile m16 x n128.
__global__ void gemm1_kernel(const float* __restrict__ x,
                             const float* __restrict__ W1l, const float* __restrict__ b1l,
                             const float* __restrict__ W1r, const float* __restrict__ b1r) {
    __shared__ float As[64 * 36];    // padded stride 36 (conflict-free frags)
    __shared__ float Bs[32 * 264];   // padded stride 264
    int t = threadIdx.x;
    int warp = t >> 5, lane = t & 31;
    int mw = warp & 3, nw = warp >> 2;   // mw: 16-row tile; nw: 128-col half
    int row0 = blockIdx.x * 64;
    int r0 = lane >> 2, c0 = lane & 3;

    float d[16][4];
#pragma unroll
    for (int i = 0; i < 16; i++)
#pragma unroll
        for (int j = 0; j < 4; j++) d[i][j] = 0.f;

    for (int kb = 0; kb < 64; kb += 32) {
#pragma unroll
        for (int u = 0; u < 8; u++) {            // As: 64x32
            int idx = t + u * 256;
            int r = idx >> 5, k = idx & 31;
            int grow = row0 + r;
            As[r * 36 + k] = (grow < NN) ? x[grow * 64 + kb + k] : 0.f;
        }
#pragma unroll
        for (int u = 0; u < 32; u++) {           // Bs: 32x256
            int idx = t + u * 256;
            int k = idx >> 8, j = idx & 255;
            Bs[k * 264 + j] = (j < 128) ? W1l[(kb + k) * 128 + j]
                                        : W1r[(kb + k) * 128 + (j - 128)];
        }
        __syncthreads();

#pragma unroll
        for (int ks = 0; ks < 4; ks++) {         // 4 k8 steps
            int ab = (mw * 16 + r0) * 36 + ks * 8 + c0;
            float af0 = As[ab];
            float af1 = As[ab + 8 * 36];
            float af2 = As[ab + 4];
            float af3 = As[ab + 8 * 36 + 4];
            uint32_t ah0, al0, ah1, al1, ah2, al2, ah3, al3;
            tf32split(af0, ah0, al0);
            tf32split(af1, ah1, al1);
            tf32split(af2, ah2, al2);
            tf32split(af3, ah3, al3);
            int kr = ks * 8 + c0;
            int nb = nw * 128 + r0;
#pragma unroll
            for (int nt = 0; nt < 16; nt++) {
                float bf0 = Bs[kr * 264 + nb + nt * 8];
                float bf1 = Bs[(kr + 4) * 264 + nb + nt * 8];
                uint32_t bh0, bl0, bh1, bl1;
                tf32split(bf0, bh0, bl0);
                tf32split(bf1, bh1, bl1);
                MMA_TF32(d[nt], ah0, ah1, ah2, ah3, bh0, bh1);
                MMA_TF32(d[nt], ah0, ah1, ah2, ah3, bl0, bl1);
                MMA_TF32(d[nt], al0, al1, al2, al3, bh0, bh1);
            }
        }
        __syncthreads();
    }

    // store: d[nt] rows (mw*16 + r0, +8), cols nw*128 + nt*8 + 2*c0 (+1)
    int grow0 = row0 + mw * 16 + r0;
#pragma unroll
    for (int nt = 0; nt < 16; nt++) {
        int j = nt * 8 + 2 * c0;                 // 0..127 within half
        if (nw == 0) {
            float bb0 = b1l[j], bb1 = b1l[j + 1];
            if (grow0 < NN)
                *(float2*)&g_xl1[grow0 * 128 + j] = make_float2(d[nt][0] + bb0, d[nt][1] + bb1);
            if (grow0 + 8 < NN)
                *(float2*)&g_xl1[(grow0 + 8) * 128 + j] = make_float2(d[nt][2] + bb0, d[nt][3] + bb1);
        } else {
            float bb0 = b1r[j], bb1 = b1r[j + 1];
            if (grow0 < NN)
                *(float2*)&g_xr1[grow0 * 128 + j] = make_float2(d[nt][0] + bb0, d[nt][1] + bb1);
            if (grow0 + 8 < NN)
                *(float2*)&g_xr1[(grow0 + 8) * 128 + j] = make_float2(d[nt][2] + bb0, d[nt][3] + bb1);
        }
    }
}

// ---------------- Layer-1 aggregation: one warp per dst node ----------------
__global__ void agg1_kernel(const float* __restrict__ att1,
                            const float* __restrict__ bias1) {
    __shared__ float sbuf[8][HC1];
    __shared__ float qbuf[8][HC1];
    int t = threadIdx.x;
    int warp = t >> 5, lane = t & 31;
    int node = blockIdx.x * 8 + warp;

    float o0 = 0.f, o1 = 0.f, o2 = 0.f, o3 = 0.f;
    if (node < NN) {
        int base = g_off[node];
        int end  = g_off[node + 1];
        if (base < 0) base = 0; if (base > EE) base = EE;
        if (end < base) end = base; if (end > EE) end = EE;
        int deg = end - base;

        float4 xr = *(const float4*)&g_xr1[node * 128 + lane * 4];
        float a0 = att1[lane * 4], a1 = att1[lane * 4 + 1];
        float a2 = att1[lane * 4 + 2], a3 = att1[lane * 4 + 3];
        float4 acc = make_float4(0.f, 0.f, 0.f, 0.f);
        float denom = 0.f;

#define EDGE1(v)                                                         \
        {                                                                \
            float m0 = (v).x + xr.x; m0 = fmaxf(m0, 0.2f * m0);          \
            float m1 = (v).y + xr.y; m1 = fmaxf(m1, 0.2f * m1);          \
            float m2 = (v).z + xr.z; m2 = fmaxf(m2, 0.2f * m2);          \
            float m3 = (v).w + xr.w; m3 = fmaxf(m3, 0.2f * m3);          \
            float p = m0 * a0 + m1 * a1 + m2 * a2 + m3 * a3;             \
            p += __shfl_xor_sync(0xffffffffu, p, 1);                     \
            p += __shfl_xor_sync(0xffffffffu, p, 2);                     \
            p += __shfl_xor_sync(0xffffffffu, p, 4);                     \
            float w = __expf(p);                                         \
            denom += w;                                                  \
            acc.x += w * (v).x; acc.y += w * (v).y;                      \
            acc.z += w * (v).z; acc.w += w * (v).w;                      \
        }

        // self loop (not stored in CSR)
        {
            float4 vs = *(const float4*)&g_xl1[node * 128 + lane * 4];
            EDGE1(vs);
        }

        for (int ch = 0; ch < deg; ch += 32) {
            int idx = ch + lane;
            int sv = 0;
            if (idx < deg) {
                sv = g_csr[base + idx];
                if ((unsigned)sv >= NN) sv = 0;
            }
            int cnt = min(32, deg - ch);
            int j = 0;
            for (; j + 4 <= cnt; j += 4) {
                int s0 = __shfl_sync(0xffffffffu, sv, j);
                int s1 = __shfl_sync(0xffffffffu, sv, j + 1);
                int s2 = __shfl_sync(0xffffffffu, sv, j + 2);
                int s3 = __shfl_sync(0xffffffffu, sv, j + 3);
                float4 v0 = *(const float4*)&g_xl1[s0 * 128 + lane * 4];
                float4 v1 = *(const float4*)&g_xl1[s1 * 128 + lane * 4];
                float4 v2 = *(const float4*)&g_xl1[s2 * 128 + lane * 4];
                float4 v3 = *(const float4*)&g_xl1[s3 * 128 + lane * 4];
                EDGE1(v0); EDGE1(v1); EDGE1(v2); EDGE1(v3);
            }
            for (; j < cnt; j++) {
                int s = __shfl_sync(0xffffffffu, sv, j);
                float4 v = *(const float4*)&g_xl1[s * 128 + lane * 4];
                EDGE1(v);
            }
        }
#undef EDGE1

        float inv = 1.f / denom;
        int c0 = lane * 4;
        o0 = fmaxf(acc.x * inv + bias1[c0],     0.f);
        o1 = fmaxf(acc.y * inv + bias1[c0 + 1], 0.f);
        o2 = fmaxf(acc.z * inv + bias1[c0 + 2], 0.f);
        o3 = fmaxf(acc.w * inv + bias1[c0 + 3], 0.f);
        *(float4*)&g_h1[node * 128 + c0] = make_float4(o0, o1, o2, o3);
    }
    int c0 = lane * 4;
    sbuf[warp][c0] = o0; sbuf[warp][c0 + 1] = o1;
    sbuf[warp][c0 + 2] = o2; sbuf[warp][c0 + 3] = o3;
    qbuf[warp][c0] = o0 * o0; qbuf[warp][c0 + 1] = o1 * o1;
    qbuf[warp][c0 + 2] = o2 * o2; qbuf[warp][c0 + 3] = o3 * o3;
    __syncthreads();
    if (t < HC1) {
        float s = 0.f, q = 0.f;
#pragma unroll
        for (int w = 0; w < 8; w++) { s += sbuf[w][t]; q += qbuf[w][t]; }
        atomicAdd(&g_stats1[t], s);
        atomicAdd(&g_stats1[HC1 + t], q);
    }
}

// ---------------- GEMM2 (tf32 tensor cores, BN1 fused):
// bn(h1)[50000,128] @ [W2l|W2r][128,128] + beff -> xl2, xr2 (fp32)
// block: 64 rows x 128 cols, 8 warps (4m x 2n), warp tile m16 x n64.
__global__ void gemm2_kernel(const float* __restrict__ bn1g, const float* __restrict__ bn1b,
                             const float* __restrict__ W2l, const float* __restrict__ b2l,
                             const float* __restrict__ W2r, const float* __restrict__ b2r) {
    __shared__ float As[64 * 36];
    __shared__ float Bs[32 * 136];
    __shared__ float sc[HC1], shv[HC1], sb2[HC1];
    int t = threadIdx.x;
    int warp = t >> 5, lane = t & 31;
    int mw = warp & 3, nw = warp >> 2;   // nw: 64-col half
    int row0 = blockIdx.x * 64;
    int r0 = lane >> 2, c0 = lane & 3;

    if (t < HC1) {
        float mu  = g_stats1[t] * (1.f / NN);
        float var = g_stats1[HC1 + t] * (1.f / NN) - mu * mu;
        float s = bn1g[t] * rsqrtf(var + EPS_);
        sc[t] = s;
        shv[t] = bn1b[t] - mu * s;
    }
    __syncthreads();
    if (t < HC1) {
        int c = t & 63;
        bool left = (t < 64);
        float s2 = 0.f;
        for (int j = 0; j < HC1; j++) {
            float w = left ? W2l[j * 64 + c] : W2r[j * 64 + c];
            s2 += shv[j] * w;
        }
        sb2[t] = (left ? b2l[c] : b2r[c]) + s2;
    }
    __syncthreads();

    float d[8][4];
#pragma unroll
    for (int i = 0; i < 8; i++)
#pragma unroll
        for (int j = 0; j < 4; j++) d[i][j] = 0.f;

    for (int kb = 0; kb < 128; kb += 32) {
#pragma unroll
        for (int u = 0; u < 8; u++) {            // As: 64x32 (BN1-scaled)
            int idx = t + u * 256;
            int r = idx >> 5, k = idx & 31;
            int grow = row0 + r;
            As[r * 36 + k] = (grow < NN) ? g_h1[grow * 128 + kb + k] * sc[kb + k] : 0.f;
        }
#pragma unroll
        for (int u = 0; u < 16; u++) {           // Bs: 32x128
            int idx = t + u * 256;
            int k = idx >> 7, j = idx & 127;
            Bs[k * 136 + j] = (j < 64) ? W2l[(kb + k) * 64 + j]
                                       : W2r[(kb + k) * 64 + (j - 64)];
        }
        __syncthreads();

#pragma unroll
        for (int ks = 0; ks < 4; ks++) {
            int ab = (mw * 16 + r0) * 36 + ks * 8 + c0;
            float af0 = As[ab];
            float af1 = As[ab + 8 * 36];
            float af2 = As[ab + 4];
            float af3 = As[ab + 8 * 36 + 4];
            uint32_t ah0, al0, ah1, al1, ah2, al2, ah3, al3;
            tf32split(af0, ah0, al0);
            tf32split(af1, ah1, al1);
            tf32split(af2, ah2, al2);
            tf32split(af3, ah3, al3);
            int kr = ks * 8 + c0;
            int nb = nw * 64 + r0;
#pragma unroll
            for (int nt = 0; nt < 8; nt++) {
                float bf0 = Bs[kr * 136 + nb + nt * 8];
                float bf1 = Bs[(kr + 4) * 136 + nb + nt * 8];
                uint32_t bh0, bl0, bh1, bl1;
                tf32split(bf0, bh0, bl0);
                tf32split(bf1, bh1, bl1);
                MMA_TF32(d[nt], ah0, ah1, ah2, ah3, bh0, bh1);
                MMA_TF32(d[nt], ah0, ah1, ah2, ah3, bl0, bl1);
                MMA_TF32(d[nt], al0, al1, al2, al3, bh0, bh1);
            }
        }
        __syncthreads();
    }

    int grow0 = row0 + mw * 16 + r0;
#pragma unroll
    for (int nt = 0; nt < 8; nt++) {
        int j = nt * 8 + 2 * c0;                 // 0..63 within half
        float bb0 = sb2[nw * 64 + j], bb1 = sb2[nw * 64 + j + 1];
        if (nw == 0) {
            if (grow0 < NN)
                *(float2*)&g_xl2[grow0 * 64 + j] = make_float2(d[nt][0] + bb0, d[nt][1] + bb1);
            if (grow0 + 8 < NN)
                *(float2*)&g_xl2[(grow0 + 8) * 64 + j] = make_float2(d[nt][2] + bb0, d[nt][3] + bb1);
        } else {
            if (grow0 < NN)
                *(float2*)&g_xr2[grow0 * 64 + j] = make_float2(d[nt][0] + bb0, d[nt][1] + bb1);
            if (grow0 + 8 < NN)
                *(float2*)&g_xr2[(grow0 + 8) * 64 + j] = make_float2(d[nt][2] + bb0, d[nt][3] + bb1);
        }
    }
}

// ---------------- Layer-2 aggregation (1 head, 64 ch) -----------------------
__global__ void agg2_kernel(const float* __restrict__ att2,
                            const float* __restrict__ bias2) {
    __shared__ float sbuf[8][C2];
    __shared__ float qbuf[8][C2];
    int t = threadIdx.x;
    int warp = t >> 5, lane = t & 31;
    int node = blockIdx.x * 8 + warp;

    float o0 = 0.f, o1 = 0.f;
    if (node < NN) {
        int base = g_off[node];
        int end  = g_off[node + 1];
        if (base < 0) base = 0; if (base > EE) base = EE;
        if (end < base) end = base; if (end > EE) end = EE;
        int deg = end - base;

        float2 xr = *(const float2*)&g_xr2[node * 64 + lane * 2];
        float a0 = att2[lane * 2], a1 = att2[lane * 2 + 1];
        float2 acc = make_float2(0.f, 0.f);
        float denom = 0.f;

#define EDGE2(v)                                                         \
        {                                                                \
            float m0 = (v).x + xr.x; m0 = fmaxf(m0, 0.2f * m0);          \
            float m1 = (v).y + xr.y; m1 = fmaxf(m1, 0.2f * m1);          \
            float p = m0 * a0 + m1 * a1;                                 \
            p += __shfl_xor_sync(0xffffffffu, p, 16);                    \
            p += __shfl_xor_sync(0xffffffffu, p, 8);                     \
            p += __shfl_xor_sync(0xffffffffu, p, 4);                     \
            p += __shfl_xor_sync(0xffffffffu, p, 2);                     \
            p += __shfl_xor_sync(0xffffffffu, p, 1);                     \
            float w = __expf(p);                                         \
            denom += w;                                                  \
            acc.x += w * (v).x;                                          \
            acc.y += w * (v).y;                                          \
        }

        // self loop
        {
            float2 vs = *(const float2*)&g_xl2[node * 64 + lane * 2];
            EDGE2(vs);
        }

        for (int ch = 0; ch < deg; ch += 32) {
            int idx = ch + lane;
            int sv = 0;
            if (idx < deg) {
                sv = g_csr[base + idx];
                if ((unsigned)sv >= NN) sv = 0;
            }
            int cnt = min(32, deg - ch);
            int j = 0;
            for (; j + 4 <= cnt; j += 4) {
                int s0 = __shfl_sync(0xffffffffu, sv, j);
                int s1 = __shfl_sync(0xffffffffu, sv, j + 1);
                int s2 = __shfl_sync(0xffffffffu, sv, j + 2);
                int s3 = __shfl_sync(0xffffffffu, sv, j + 3);
                float2 v0 = *(const float2*)&g_xl2[s0 * 64 + lane * 2];
                float2 v1 = *(const float2*)&g_xl2[s1 * 64 + lane * 2];
                float2 v2 = *(const float2*)&g_xl2[s2 * 64 + lane * 2];
                float2 v3 = *(const float2*)&g_xl2[s3 * 64 + lane * 2];
                EDGE2(v0); EDGE2(v1); EDGE2(v2); EDGE2(v3);
            }
            for (; j < cnt; j++) {
                int s = __shfl_sync(0xffffffffu, sv, j);
                float2 v = *(const float2*)&g_xl2[s * 64 + lane * 2];
                EDGE2(v);
            }
        }
#undef EDGE2

        float inv = 1.f / denom;
        int c0 = lane * 2;
        o0 = fmaxf(acc.x * inv + bias2[c0],     0.f);
        o1 = fmaxf(acc.y * inv + bias2[c0 + 1], 0.f);
        *(float2*)&g_h2[node * 64 + c0] = make_float2(o0, o1);
    }
    int c0 = lane * 2;
    sbuf[warp][c0] = o0; sbuf[warp][c0 + 1] = o1;
    qbuf[warp][c0] = o0 * o0; qbuf[warp][c0 + 1] = o1 * o1;
    __syncthreads();
    if (t < C2) {
        float s = 0.f, q = 0.f;
#pragma unroll
        for (int w = 0; w < 8; w++) { s += sbuf[w][t]; q += qbuf[w][t]; }
        atomicAdd(&g_stats2[t], s);
        atomicAdd(&g_stats2[C2 + t], q);
    }
}

// ---------------- pooling (BN2 + sum/mean/max) + final linear ---------------
__device__ __forceinline__ int lbound_i(const int* a, int n, int key) {
    int lo = 0, hi = n;
    while (lo < hi) {
        int m = (lo + hi) >> 1;
        if (a[m] < key) lo = m + 1; else hi = m;
    }
    return lo;
}

__global__ void pool_kernel(const int* __restrict__ batch,
                            const float* __restrict__ bn2g, const float* __restrict__ bn2b,
                            const float* __restrict__ linw, const float* __restrict__ linb,
                            float* __restrict__ out) {
    __shared__ float red[4][C2];
    __shared__ float rmx[4][C2];
    __shared__ float sfeat[3 * C2];
    int g = blockIdx.x;
    int t = threadIdx.x;
    int c = t & 63;
    int r = t >> 6;   // 0..3

    int s0 = lbound_i(batch, NN, g);
    int s1 = lbound_i(batch, NN, g + 1);

    float mu  = g_stats2[c] * (1.f / NN);
    float var = g_stats2[C2 + c] * (1.f / NN) - mu * mu;
    float sc = bn2g[c] * rsqrtf(var + EPS_);
    float sh = bn2b[c] - mu * sc;

    float sum = 0.f, mx = -3.402823466e38f;
    for (int v = s0 + r; v < s1; v += 4) {
        float y = g_h2[v * 64 + c] * sc + sh;
        sum += y;
        mx = fmaxf(mx, y);
    }
    red[r][c] = sum;
    rmx[r][c] = mx;
    __syncthreads();
    if (r == 0) {
        float tot = red[0][c] + red[1][c] + red[2][c] + red[3][c];
        int cnt = s1 - s0;
        sfeat[c] = tot;
        sfeat[64 + c] = tot / (float)max(cnt, 1);
        sfeat[128 + c] = fmaxf(fmaxf(rmx[0][c], rmx[1][c]),
                               fmaxf(rmx[2][c], rmx[3][c]));
    }
    __syncthreads();
    if (t < 64) {
        int o = t >> 5;     // output 0 or 1
        int l = t & 31;
        float p = 0.f;
        for (int f = l; f < 192; f += 32) p += sfeat[f] * linw[f * 2 + o];
        p += __shfl_xor_sync(0xffffffffu, p, 16);
        p += __shfl_xor_sync(0xffffffffu, p, 8);
        p += __shfl_xor_sync(0xffffffffu, p, 4);
        p += __shfl_xor_sync(0xffffffffu, p, 2);
        p += __shfl_xor_sync(0xffffffffu, p, 1);
        if (l == 0) out[g * 2 + o] = p + linb[o];
    }
}

// ---------------- launch -----------------------------------------------------
extern "C" void kernel_launch(void* const* d_in, const int* in_sizes, int n_in,
                              void* d_out, int out_size) {
    const float* x     = (const float*)d_in[0];
    const int*   ei    = (const int*)d_in[1];    // int32 (JAX x64 disabled)
    const int*   batch = (const int*)d_in[2];    // int32
    const float* W1l  = (const float*)d_in[3];
    const float* b1l  = (const float*)d_in[4];
    const float* W1r  = (const float*)d_in[5];
    const float* b1r  = (const float*)d_in[6];
    const float* att1 = (const float*)d_in[7];
    const float* bias1= (const float*)d_in[8];
    const float* W2l  = (const float*)d_in[9];
    const float* b2l  = (const float*)d_in[10];
    const float* W2r  = (const float*)d_in[11];
    const float* b2r  = (const float*)d_in[12];
    const float* att2 = (const float*)d_in[13];
    const float* bias2= (const float*)d_in[14];
    const float* bn1g = (const float*)d_in[15];
    const float* bn1b = (const float*)d_in[16];
    const float* bn2g = (const float*)d_in[17];
    const float* bn2b = (const float*)d_in[18];
    const float* linw = (const float*)d_in[19];
    const float* linb = (const float*)d_in[20];
    float* out = (float*)d_out;

    prep_kernel<<<(NN + 255) / 256, 256>>>();                       // 0
    hist_kernel<<<(EE / 4 + 255) / 256, 256>>>(ei);                 // 1
    scan_kernel<<<NBLK, 256>>>();                                   // 2
    gemm1_kernel<<<(NN + 63) / 64, 256>>>(x, W1l, b1l, W1r, b1r);   // 3  <- ncu window
    scatter_kernel<<<(EE / 4 + 255) / 256, 256>>>(ei);              // 4
    agg1_kernel<<<(NN + 7) / 8, 256>>>(att1, bias1);                // 5
    gemm2_kernel<<<(NN + 63) / 64, 256>>>(bn1g, bn1b, W2l, b2l, W2r, b2r); // 6
    agg2_kernel<<<(NN + 7) / 8, 256>>>(att2, bias2);                // 7
    pool_kernel<<<GG, 256>>>(batch, bn2g, bn2b, linw, linb, out);   // 8
}

// round 16
// speedup vs baseline: 1.5404x; 1.5404x over previous
#include <cuda_runtime.h>
#include <cstdint>

#define NN 50000
#define EE 1600000
#define GG 128
#define HC1 128      // 4 heads * 32 ch
#define C2 64
#define EPS_ 1e-5f
#define NBLK 196     // ceil(50000/256)

// ---------------- scratch (static device memory; no allocs) ----------------
__device__ __align__(16) float g_xl1[NN * HC1];
__device__ __align__(16) float g_xr1[NN * HC1];
__device__ __align__(16) float g_h1 [NN * HC1];
__device__ __align__(16) float g_xl2[NN * C2];
__device__ __align__(16) float g_xr2[NN * C2];
__device__ __align__(16) float g_h2 [NN * C2];
__device__ int   g_deg[NN];
__device__ int   g_off[NN + 1];
__device__ int   g_cur[NN];
__device__ int   g_csr[EE];
__device__ unsigned long long g_scan_state[NBLK];  // (inclusive<<32)|flag
__device__ float g_stats1[2 * HC1];
__device__ float g_stats2[2 * C2];

// ---------------- tf32 helpers ----------------------------------------------
__device__ __forceinline__ void tf32split(float v, uint32_t& hi, uint32_t& lo) {
    uint32_t h;
    asm("cvt.rna.tf32.f32 %0, %1;" : "=r"(h) : "f"(v));
    float r = v - __uint_as_float(h);
    uint32_t l;
    asm("cvt.rna.tf32.f32 %0, %1;" : "=r"(l) : "f"(r));
    hi = h; lo = l;
}

#define MMA_TF32(d, a0, a1, a2, a3, b0, b1)                                   \
    asm volatile("mma.sync.aligned.m16n8k8.row.col.f32.tf32.tf32.f32 "        \
                 "{%0,%1,%2,%3}, {%4,%5,%6,%7}, {%8,%9}, {%0,%1,%2,%3};"      \
                 : "+f"(d[0]), "+f"(d[1]), "+f"(d[2]), "+f"(d[3])             \
                 : "r"(a0), "r"(a1), "r"(a2), "r"(a3), "r"(b0), "r"(b1))

// ---------------- prep: zero deg, scan state, BN stats ----------------------
__global__ void prep_kernel() {
    int i = blockIdx.x * blockDim.x + threadIdx.x;
    if (i < NN) g_deg[i] = 0;
    if (i < NBLK) g_scan_state[i] = 0ull;
    if (i < 2 * HC1) g_stats1[i] = 0.f;
    if (i < 2 * C2)  g_stats2[i] = 0.f;
}

// ---------------- in-degree histogram (4 edges/thread, int4 loads) ---------
__global__ void hist_kernel(const int* __restrict__ ei) {
    int e4 = blockIdx.x * blockDim.x + threadIdx.x;
    if (e4 * 4 < EE) {
        int4 d4 = *(const int4*)&ei[EE + e4 * 4];
        int d0 = d4.x, d1 = d4.y, d2 = d4.z, d3 = d4.w;
        if ((unsigned)d0 >= NN) d0 = 0;
        if ((unsigned)d1 >= NN) d1 = 0;
        if ((unsigned)d2 >= NN) d2 = 0;
        if ((unsigned)d3 >= NN) d3 = 0;
        atomicAdd(&g_deg[d0], 1);
        atomicAdd(&g_deg[d1], 1);
        atomicAdd(&g_deg[d2], 1);
        atomicAdd(&g_deg[d3], 1);
    }
}

// ---------------- single-pass decoupled-lookback exclusive scan -------------
__global__ void scan_kernel() {
    __shared__ int s[256];
    __shared__ long long base_s;
    int t = threadIdx.x;
    int b = blockIdx.x;
    int i = b * 256 + t;

    int v = (i < NN) ? g_deg[i] : 0;
    s[t] = v;
    __syncthreads();
    for (int o = 1; o < 256; o <<= 1) {
        int tv = (t >= o) ? s[t - o] : 0;
        __syncthreads();
        s[t] += tv;
        __syncthreads();
    }
    int blockAgg = s[255];

    if (t == 0) {
        long long run = 0;
        if (b == 0) {
            atomicExch(&g_scan_state[0], ((unsigned long long)blockAgg << 32) | 2ull);
        } else {
            atomicExch(&g_scan_state[b], ((unsigned long long)blockAgg << 32) | 1ull);
            int p = b - 1;
            while (p >= 0) {
                unsigned long long st;
                do {
                    st = *(volatile unsigned long long*)&g_scan_state[p];
                } while ((st & 3ull) == 0ull);
                run += (long long)(st >> 32);
                if ((st & 3ull) == 2ull) break;
                p--;
            }
            atomicExch(&g_scan_state[b],
                       ((unsigned long long)(run + blockAgg) << 32) | 2ull);
        }
        base_s = run;
    }
    __syncthreads();
    long long base = base_s;
    int e = (int)base + s[t] - v;       // exclusive prefix
    if (i < NN) { g_off[i] = e; g_cur[i] = e; }
    if (b == NBLK - 1 && t == 255) g_off[NN] = (int)base + blockAgg;
}

// ---------------- CSR scatter (edges only; self loops handled in agg) -------
__global__ void scatter_kernel(const int* __restrict__ ei) {
    int i = blockIdx.x * blockDim.x + threadIdx.x;
    const int E4 = EE / 4;
    if (i < E4) {
        int4 s4 = *(const int4*)&ei[i * 4];
        int4 d4 = *(const int4*)&ei[EE + i * 4];
        int ss[4] = {s4.x, s4.y, s4.z, s4.w};
        int dd[4] = {d4.x, d4.y, d4.z, d4.w};
#pragma unroll
        for (int k = 0; k < 4; k++) {
            int sv = ss[k], dv = dd[k];
            if ((unsigned)sv >= NN) sv = 0;
            if ((unsigned)dv >= NN) dv = 0;
            int pos = atomicAdd(&g_cur[dv], 1);
            if ((unsigned)pos < EE) g_csr[pos] = sv;
        }
    }
}

// ---------------- GEMM1 (tf32 MMA, pre-split hi/lo in smem, BK=16):
// x[50000,64] @ [W1l|W1r][64,256] + bias -> xl1, xr1 (fp32)
// block 64 rows x 256 cols, 8 warps (4m x 2n), warp tile m16 x n128.
__global__ void gemm1_kernel(const float* __restrict__ x,
                             const float* __restrict__ W1l, const float* __restrict__ b1l,
                             const float* __restrict__ W1r, const float* __restrict__ b1r) {
    __shared__ uint32_t Ah[64 * 20], Al[64 * 20];      // 64x16, stride 20
    __shared__ uint32_t Bh[16 * 264], Bl[16 * 264];    // 16x256, stride 264
    int t = threadIdx.x;
    int warp = t >> 5, lane = t & 31;
    int mw = warp & 3, nw = warp >> 2;
    int row0 = blockIdx.x * 64;
    int r0 = lane >> 2, c0 = lane & 3;

    float d[16][4];
#pragma unroll
    for (int i = 0; i < 16; i++)
#pragma unroll
        for (int j = 0; j < 4; j++) d[i][j] = 0.f;

    for (int kb = 0; kb < 64; kb += 16) {
#pragma unroll
        for (int u = 0; u < 4; u++) {                // A: 64x16
            int idx = t + u * 256;
            int r = idx >> 4, k = idx & 15;
            int grow = row0 + r;
            float v = (grow < NN) ? x[grow * 64 + kb + k] : 0.f;
            uint32_t hi, lo; tf32split(v, hi, lo);
            Ah[r * 20 + k] = hi; Al[r * 20 + k] = lo;
        }
#pragma unroll
        for (int u = 0; u < 16; u++) {               // B: 16x256
            int idx = t + u * 256;
            int k = idx >> 8, j = idx & 255;
            float v = (j < 128) ? W1l[(kb + k) * 128 + j]
                                : W1r[(kb + k) * 128 + (j - 128)];
            uint32_t hi, lo; tf32split(v, hi, lo);
            Bh[k * 264 + j] = hi; Bl[k * 264 + j] = lo;
        }
        __syncthreads();

#pragma unroll
        for (int ks = 0; ks < 2; ks++) {
            int ar = (mw * 16 + r0) * 20 + ks * 8 + c0;
            uint32_t ah0 = Ah[ar],           ah1 = Ah[ar + 8 * 20];
            uint32_t ah2 = Ah[ar + 4],       ah3 = Ah[ar + 8 * 20 + 4];
            uint32_t al0 = Al[ar],           al1 = Al[ar + 8 * 20];
            uint32_t al2 = Al[ar + 4],       al3 = Al[ar + 8 * 20 + 4];
            int kr = ks * 8 + c0;
            int nb = nw * 128 + r0;
#pragma unroll
            for (int nt = 0; nt < 16; nt++) {
                uint32_t bh0 = Bh[kr * 264 + nb + nt * 8];
                uint32_t bh1 = Bh[(kr + 4) * 264 + nb + nt * 8];
                uint32_t bl0 = Bl[kr * 264 + nb + nt * 8];
                uint32_t bl1 = Bl[(kr + 4) * 264 + nb + nt * 8];
                MMA_TF32(d[nt], ah0, ah1, ah2, ah3, bh0, bh1);
                MMA_TF32(d[nt], ah0, ah1, ah2, ah3, bl0, bl1);
                MMA_TF32(d[nt], al0, al1, al2, al3, bh0, bh1);
            }
        }
        __syncthreads();
    }

    int grow0 = row0 + mw * 16 + r0;
#pragma unroll
    for (int nt = 0; nt < 16; nt++) {
        int j = nt * 8 + 2 * c0;                     // 0..127 within half
        if (nw == 0) {
            float bb0 = b1l[j], bb1 = b1l[j + 1];
            if (grow0 < NN)
                *(float2*)&g_xl1[grow0 * 128 + j] = make_float2(d[nt][0] + bb0, d[nt][1] + bb1);
            if (grow0 + 8 < NN)
                *(float2*)&g_xl1[(grow0 + 8) * 128 + j] = make_float2(d[nt][2] + bb0, d[nt][3] + bb1);
        } else {
            float bb0 = b1r[j], bb1 = b1r[j + 1];
            if (grow0 < NN)
                *(float2*)&g_xr1[grow0 * 128 + j] = make_float2(d[nt][0] + bb0, d[nt][1] + bb1);
            if (grow0 + 8 < NN)
                *(float2*)&g_xr1[(grow0 + 8) * 128 + j] = make_float2(d[nt][2] + bb0, d[nt][3] + bb1);
        }
    }
}

// ---------------- Layer-1 aggregation: one warp per dst node ----------------
__global__ void agg1_kernel(const float* __restrict__ att1,
                            const float* __restrict__ bias1) {
    __shared__ float sbuf[8][HC1];
    __shared__ float qbuf[8][HC1];
    int t = threadIdx.x;
    int warp = t >> 5, lane = t & 31;
    int node = blockIdx.x * 8 + warp;

    float o0 = 0.f, o1 = 0.f, o2 = 0.f, o3 = 0.f;
    if (node < NN) {
        int base = g_off[node];
        int end  = g_off[node + 1];
        if (base < 0) base = 0; if (base > EE) base = EE;
        if (end < base) end = base; if (end > EE) end = EE;
        int deg = end - base;

        float4 xr = *(const float4*)&g_xr1[node * 128 + lane * 4];
        float a0 = att1[lane * 4], a1 = att1[lane * 4 + 1];
        float a2 = att1[lane * 4 + 2], a3 = att1[lane * 4 + 3];
        float4 acc = make_float4(0.f, 0.f, 0.f, 0.f);
        float denom = 0.f;

#define EDGE1(v)                                                         \
        {                                                                \
            float m0 = (v).x + xr.x; m0 = fmaxf(m0, 0.2f * m0);          \
            float m1 = (v).y + xr.y; m1 = fmaxf(m1, 0.2f * m1);          \
            float m2 = (v).z + xr.z; m2 = fmaxf(m2, 0.2f * m2);          \
            float m3 = (v).w + xr.w; m3 = fmaxf(m3, 0.2f * m3);          \
            float p = m0 * a0 + m1 * a1 + m2 * a2 + m3 * a3;             \
            p += __shfl_xor_sync(0xffffffffu, p, 1);                     \
            p += __shfl_xor_sync(0xffffffffu, p, 2);                     \
            p += __shfl_xor_sync(0xffffffffu, p, 4);                     \
            float w = __expf(p);                                         \
            denom += w;                                                  \
            acc.x += w * (v).x; acc.y += w * (v).y;                      \
            acc.z += w * (v).z; acc.w += w * (v).w;                      \
        }

        // self loop (not stored in CSR)
        {
            float4 vs = *(const float4*)&g_xl1[node * 128 + lane * 4];
            EDGE1(vs);
        }

        for (int ch = 0; ch < deg; ch += 32) {
            int idx = ch + lane;
            int sv = 0;
            if (idx < deg) {
                sv = g_csr[base + idx];
                if ((unsigned)sv >= NN) sv = 0;
            }
            int cnt = min(32, deg - ch);
            int j = 0;
            for (; j + 4 <= cnt; j += 4) {
                int s0 = __shfl_sync(0xffffffffu, sv, j);
                int s1 = __shfl_sync(0xffffffffu, sv, j + 1);
                int s2 = __shfl_sync(0xffffffffu, sv, j + 2);
                int s3 = __shfl_sync(0xffffffffu, sv, j + 3);
                float4 v0 = *(const float4*)&g_xl1[s0 * 128 + lane * 4];
                float4 v1 = *(const float4*)&g_xl1[s1 * 128 + lane * 4];
                float4 v2 = *(const float4*)&g_xl1[s2 * 128 + lane * 4];
                float4 v3 = *(const float4*)&g_xl1[s3 * 128 + lane * 4];
                EDGE1(v0); EDGE1(v1); EDGE1(v2); EDGE1(v3);
            }
            for (; j < cnt; j++) {
                int s = __shfl_sync(0xffffffffu, sv, j);
                float4 v = *(const float4*)&g_xl1[s * 128 + lane * 4];
                EDGE1(v);
            }
        }
#undef EDGE1

        float inv = 1.f / denom;
        int c0 = lane * 4;
        o0 = fmaxf(acc.x * inv + bias1[c0],     0.f);
        o1 = fmaxf(acc.y * inv + bias1[c0 + 1], 0.f);
        o2 = fmaxf(acc.z * inv + bias1[c0 + 2], 0.f);
        o3 = fmaxf(acc.w * inv + bias1[c0 + 3], 0.f);
        *(float4*)&g_h1[node * 128 + c0] = make_float4(o0, o1, o2, o3);
    }
    int c0 = lane * 4;
    sbuf[warp][c0] = o0; sbuf[warp][c0 + 1] = o1;
    sbuf[warp][c0 + 2] = o2; sbuf[warp][c0 + 3] = o3;
    qbuf[warp][c0] = o0 * o0; qbuf[warp][c0 + 1] = o1 * o1;
    qbuf[warp][c0 + 2] = o2 * o2; qbuf[warp][c0 + 3] = o3 * o3;
    __syncthreads();
    if (t < HC1) {
        float s = 0.f, q = 0.f;
#pragma unroll
        for (int w = 0; w < 8; w++) { s += sbuf[w][t]; q += qbuf[w][t]; }
        atomicAdd(&g_stats1[t], s);
        atomicAdd(&g_stats1[HC1 + t], q);
    }
}

// ---------------- GEMM2 (tf32 MMA, pre-split, BN1 fused, BK=16):
// bn(h1)[50000,128] @ [W2l|W2r][128,128] + beff -> xl2, xr2 (fp32)
__global__ void gemm2_kernel(const float* __restrict__ bn1g, const float* __restrict__ bn1b,
                             const float* __restrict__ W2l, const float* __restrict__ b2l,
                             const float* __restrict__ W2r, const float* __restrict__ b2r) {
    __shared__ uint32_t Ah[64 * 20], Al[64 * 20];     // 64x16, stride 20
    __shared__ uint32_t Bh[16 * 136], Bl[16 * 136];   // 16x128, stride 136
    __shared__ float sc[HC1], shv[HC1], sb2[HC1];
    int t = threadIdx.x;
    int warp = t >> 5, lane = t & 31;
    int mw = warp & 3, nw = warp >> 2;
    int row0 = blockIdx.x * 64;
    int r0 = lane >> 2, c0 = lane & 3;

    if (t < HC1) {
        float mu  = g_stats1[t] * (1.f / NN);
        float var = g_stats1[HC1 + t] * (1.f / NN) - mu * mu;
        float s = bn1g[t] * rsqrtf(var + EPS_);
        sc[t] = s;
        shv[t] = bn1b[t] - mu * s;
    }
    __syncthreads();
    if (t < HC1) {
        int c = t & 63;
        bool left = (t < 64);
        float s2 = 0.f;
        for (int j = 0; j < HC1; j++) {
            float w = left ? W2l[j * 64 + c] : W2r[j * 64 + c];
            s2 += shv[j] * w;
        }
        sb2[t] = (left ? b2l[c] : b2r[c]) + s2;
    }
    __syncthreads();

    float d[8][4];
#pragma unroll
    for (int i = 0; i < 8; i++)
#pragma unroll
        for (int j = 0; j < 4; j++) d[i][j] = 0.f;

    for (int kb = 0; kb < 128; kb += 16) {
#pragma unroll
        for (int u = 0; u < 4; u++) {                // A: 64x16 (BN1-scaled)
            int idx = t + u * 256;
            int r = idx >> 4, k = idx & 15;
            int grow = row0 + r;
            float v = (grow < NN) ? g_h1[grow * 128 + kb + k] * sc[kb + k] : 0.f;
            uint32_t hi, lo; tf32split(v, hi, lo);
            Ah[r * 20 + k] = hi; Al[r * 20 + k] = lo;
        }
#pragma unroll
        for (int u = 0; u < 8; u++) {                // B: 16x128
            int idx = t + u * 256;
            int k = idx >> 7, j = idx & 127;
            float v = (j < 64) ? W2l[(kb + k) * 64 + j]
                               : W2r[(kb + k) * 64 + (j - 64)];
            uint32_t hi, lo; tf32split(v, hi, lo);
            Bh[k * 136 + j] = hi; Bl[k * 136 + j] = lo;
        }
        __syncthreads();

#pragma unroll
        for (int ks = 0; ks < 2; ks++) {
            int ar = (mw * 16 + r0) * 20 + ks * 8 + c0;
            uint32_t ah0 = Ah[ar],           ah1 = Ah[ar + 8 * 20];
            uint32_t ah2 = Ah[ar + 4],       ah3 = Ah[ar + 8 * 20 + 4];
            uint32_t al0 = Al[ar],           al1 = Al[ar + 8 * 20];
            uint32_t al2 = Al[ar + 4],       al3 = Al[ar + 8 * 20 + 4];
            int kr = ks * 8 + c0;
            int nb = nw * 64 + r0;
#pragma unroll
            for (int nt = 0; nt < 8; nt++) {
                uint32_t bh0 = Bh[kr * 136 + nb + nt * 8];
                uint32_t bh1 = Bh[(kr + 4) * 136 + nb + nt * 8];
                uint32_t bl0 = Bl[kr * 136 + nb + nt * 8];
                uint32_t bl1 = Bl[(kr + 4) * 136 + nb + nt * 8];
                MMA_TF32(d[nt], ah0, ah1, ah2, ah3, bh0, bh1);
                MMA_TF32(d[nt], ah0, ah1, ah2, ah3, bl0, bl1);
                MMA_TF32(d[nt], al0, al1, al2, al3, bh0, bh1);
            }
        }
        __syncthreads();
    }

    int grow0 = row0 + mw * 16 + r0;
#pragma unroll
    for (int nt = 0; nt < 8; nt++) {
        int j = nt * 8 + 2 * c0;                     // 0..63 within half
        float bb0 = sb2[nw * 64 + j], bb1 = sb2[nw * 64 + j + 1];
        if (nw == 0) {
            if (grow0 < NN)
                *(float2*)&g_xl2[grow0 * 64 + j] = make_float2(d[nt][0] + bb0, d[nt][1] + bb1);
            if (grow0 + 8 < NN)
                *(float2*)&g_xl2[(grow0 + 8) * 64 + j] = make_float2(d[nt][2] + bb0, d[nt][3] + bb1);
        } else {
            if (grow0 < NN)
                *(float2*)&g_xr2[grow0 * 64 + j] = make_float2(d[nt][0] + bb0, d[nt][1] + bb1);
            if (grow0 + 8 < NN)
                *(float2*)&g_xr2[(grow0 + 8) * 64 + j] = make_float2(d[nt][2] + bb0, d[nt][3] + bb1);
        }
    }
}

// ---------------- Layer-2 aggregation (1 head, 64 ch) -----------------------
__global__ void agg2_kernel(const float* __restrict__ att2,
                            const float* __restrict__ bias2) {
    __shared__ float sbuf[8][C2];
    __shared__ float qbuf[8][C2];
    int t = threadIdx.x;
    int warp = t >> 5, lane = t & 31;
    int node = blockIdx.x * 8 + warp;

    float o0 = 0.f, o1 = 0.f;
    if (node < NN) {
        int base = g_off[node];
        int end  = g_off[node + 1];
        if (base < 0) base = 0; if (base > EE) base = EE;
        if (end < base) end = base; if (end > EE) end = EE;
        int deg = end - base;

        float2 xr = *(const float2*)&g_xr2[node * 64 + lane * 2];
        float a0 = att2[lane * 2], a1 = att2[lane * 2 + 1];
        float2 acc = make_float2(0.f, 0.f);
        float denom = 0.f;

#define EDGE2(v)                                                         \
        {                                                                \
            float m0 = (v).x + xr.x; m0 = fmaxf(m0, 0.2f * m0);          \
            float m1 = (v).y + xr.y; m1 = fmaxf(m1, 0.2f * m1);          \
            float p = m0 * a0 + m1 * a1;                                 \
            p += __shfl_xor_sync(0xffffffffu, p, 16);                    \
            p += __shfl_xor_sync(0xffffffffu, p, 8);                     \
            p += __shfl_xor_sync(0xffffffffu, p, 4);                     \
            p += __shfl_xor_sync(0xffffffffu, p, 2);                     \
            p += __shfl_xor_sync(0xffffffffu, p, 1);                     \
            float w = __expf(p);                                         \
            denom += w;                                                  \
            acc.x += w * (v).x;                                          \
            acc.y += w * (v).y;                                          \
        }

        // self loop
        {
            float2 vs = *(const float2*)&g_xl2[node * 64 + lane * 2];
            EDGE2(vs);
        }

        for (int ch = 0; ch < deg; ch += 32) {
            int idx = ch + lane;
            int sv = 0;
            if (idx < deg) {
                sv = g_csr[base + idx];
                if ((unsigned)sv >= NN) sv = 0;
            }
            int cnt = min(32, deg - ch);
            int j = 0;
            for (; j + 4 <= cnt; j += 4) {
                int s0 = __shfl_sync(0xffffffffu, sv, j);
                int s1 = __shfl_sync(0xffffffffu, sv, j + 1);
                int s2 = __shfl_sync(0xffffffffu, sv, j + 2);
                int s3 = __shfl_sync(0xffffffffu, sv, j + 3);
                float2 v0 = *(const float2*)&g_xl2[s0 * 64 + lane * 2];
                float2 v1 = *(const float2*)&g_xl2[s1 * 64 + lane * 2];
                float2 v2 = *(const float2*)&g_xl2[s2 * 64 + lane * 2];
                float2 v3 = *(const float2*)&g_xl2[s3 * 64 + lane * 2];
                EDGE2(v0); EDGE2(v1); EDGE2(v2); EDGE2(v3);
            }
            for (; j < cnt; j++) {
                int s = __shfl_sync(0xffffffffu, sv, j);
                float2 v = *(const float2*)&g_xl2[s * 64 + lane * 2];
                EDGE2(v);
            }
        }
#undef EDGE2

        float inv = 1.f / denom;
        int c0 = lane * 2;
        o0 = fmaxf(acc.x * inv + bias2[c0],     0.f);
        o1 = fmaxf(acc.y * inv + bias2[c0 + 1], 0.f);
        *(float2*)&g_h2[node * 64 + c0] = make_float2(o0, o1);
    }
    int c0 = lane * 2;
    sbuf[warp][c0] = o0; sbuf[warp][c0 + 1] = o1;
    qbuf[warp][c0] = o0 * o0; qbuf[warp][c0 + 1] = o1 * o1;
    __syncthreads();
    if (t < C2) {
        float s = 0.f, q = 0.f;
#pragma unroll
        for (int w = 0; w < 8; w++) { s += sbuf[w][t]; q += qbuf[w][t]; }
        atomicAdd(&g_stats2[t], s);
        atomicAdd(&g_stats2[C2 + t], q);
    }
}

// ---------------- pooling (BN2 + sum/mean/max) + final linear ---------------
__device__ __forceinline__ int lbound_i(const int* a, int n, int key) {
    int lo = 0, hi = n;
    while (lo < hi) {
        int m = (lo + hi) >> 1;
        if (a[m] < key) lo = m + 1; else hi = m;
    }
    return lo;
}

__global__ void pool_kernel(const int* __restrict__ batch,
                            const float* __restrict__ bn2g, const float* __restrict__ bn2b,
                            const float* __restrict__ linw, const float* __restrict__ linb,
                            float* __restrict__ out) {
    __shared__ float red[4][C2];
    __shared__ float rmx[4][C2];
    __shared__ float sfeat[3 * C2];
    int g = blockIdx.x;
    int t = threadIdx.x;
    int c = t & 63;
    int r = t >> 6;   // 0..3

    int s0 = lbound_i(batch, NN, g);
    int s1 = lbound_i(batch, NN, g + 1);

    float mu  = g_stats2[c] * (1.f / NN);
    float var = g_stats2[C2 + c] * (1.f / NN) - mu * mu;
    float sc = bn2g[c] * rsqrtf(var + EPS_);
    float sh = bn2b[c] - mu * sc;

    float sum = 0.f, mx = -3.402823466e38f;
    for (int v = s0 + r; v < s1; v += 4) {
        float y = g_h2[v * 64 + c] * sc + sh;
        sum += y;
        mx = fmaxf(mx, y);
    }
    red[r][c] = sum;
    rmx[r][c] = mx;
    __syncthreads();
    if (r == 0) {
        float tot = red[0][c] + red[1][c] + red[2][c] + red[3][c];
        int cnt = s1 - s0;
        sfeat[c] = tot;
        sfeat[64 + c] = tot / (float)max(cnt, 1);
        sfeat[128 + c] = fmaxf(fmaxf(rmx[0][c], rmx[1][c]),
                               fmaxf(rmx[2][c], rmx[3][c]));
    }
    __syncthreads();
    if (t < 64) {
        int o = t >> 5;     // output 0 or 1
        int l = t & 31;
        float p = 0.f;
        for (int f = l; f < 192; f += 32) p += sfeat[f] * linw[f * 2 + o];
        p += __shfl_xor_sync(0xffffffffu, p, 16);
        p += __shfl_xor_sync(0xffffffffu, p, 8);
        p += __shfl_xor_sync(0xffffffffu, p, 4);
        p += __shfl_xor_sync(0xffffffffu, p, 2);
        p += __shfl_xor_sync(0xffffffffu, p, 1);
        if (l == 0) out[g * 2 + o] = p + linb[o];
    }
}

// ---------------- launch -----------------------------------------------------
extern "C" void kernel_launch(void* const* d_in, const int* in_sizes, int n_in,
                              void* d_out, int out_size) {
    const float* x     = (const float*)d_in[0];
    const int*   ei    = (const int*)d_in[1];    // int32 (JAX x64 disabled)
    const int*   batch = (const int*)d_in[2];    // int32
    const float* W1l  = (const float*)d_in[3];
    const float* b1l  = (const float*)d_in[4];
    const float* W1r  = (const float*)d_in[5];
    const float* b1r  = (const float*)d_in[6];
    const float* att1 = (const float*)d_in[7];
    const float* bias1= (const float*)d_in[8];
    const float* W2l  = (const float*)d_in[9];
    const float* b2l  = (const float*)d_in[10];
    const float* W2r  = (const float*)d_in[11];
    const float* b2r  = (const float*)d_in[12];
    const float* att2 = (const float*)d_in[13];
    const float* bias2= (const float*)d_in[14];
    const float* bn1g = (const float*)d_in[15];
    const float* bn1b = (const float*)d_in[16];
    const float* bn2g = (const float*)d_in[17];
    const float* bn2b = (const float*)d_in[18];
    const float* linw = (const float*)d_in[19];
    const float* linb = (const float*)d_in[20];
    float* out = (float*)d_out;

    prep_kernel<<<(NN + 255) / 256, 256>>>();                       // 1
    hist_kernel<<<(EE / 4 + 255) / 256, 256>>>(ei);                 // 2
    scan_kernel<<<NBLK, 256>>>();                                   // 3
    gemm1_kernel<<<(NN + 63) / 64, 256>>>(x, W1l, b1l, W1r, b1r);   // 4  <- ncu window
    scatter_kernel<<<(EE / 4 + 255) / 256, 256>>>(ei);              // 5
    agg1_kernel<<<(NN + 7) / 8, 256>>>(att1, bias1);                // 6
    gemm2_kernel<<<(NN + 63) / 64, 256>>>(bn1g, bn1b, W2l, b2l, W2r, b2r); // 7
    agg2_kernel<<<(NN + 7) / 8, 256>>>(att2, bias2);                // 8
    pool_kernel<<<GG, 256>>>(batch, bn2g, bn2b, linw, linb, out);   // 9
}